// round 3
// baseline (speedup 1.0000x reference)
#include <cuda_runtime.h>

// B=512 rows, L=16 labels, N=8192 values. Single fused kernel.
// loss = sum_{i,j} W[i,j] * S[i,j]
//   W[i,j] = sum_l inv[l] * [yt[i,l]==1] * [yt[j,l]==0],  inv[l]=1/((np*nn)^2 * 256)
//   S[i,j] = 0.5 * ( sum|t| + 256 - 16*sx[i] + 16*sx[j] ),  t = 1 - x[i,c] + x[j,d]
// (relu(t) = (t+|t|)/2 exactly; sum t has closed form.)

#define NROW 512
#define NL   16
#define TI   16
#define GB   (NROW / TI)          // 32
#define NBLK (GB * GB)            // 1024

__device__ float        g_part[NBLK];
__device__ unsigned int g_cnt = 0;

// ---- packed f32x2 helpers -------------------------------------------------
__device__ __forceinline__ unsigned long long pk2(float lo, float hi) {
    unsigned long long r;
    asm("mov.b64 %0, {%1, %2};" : "=l"(r) : "f"(lo), "f"(hi));
    return r;
}
__device__ __forceinline__ unsigned long long addx2(unsigned long long a,
                                                    unsigned long long b) {
    unsigned long long r;
    asm("add.rn.f32x2 %0, %1, %2;" : "=l"(r) : "l"(a), "l"(b));
    return r;
}
__device__ __forceinline__ void unpk2(unsigned long long v, float& lo, float& hi) {
    asm("mov.b64 {%0, %1}, %2;" : "=f"(lo), "=f"(hi) : "l"(v));
}

__global__ void __launch_bounds__(256) k_all(const int* __restrict__ yt,
                                             const float* __restrict__ yp,
                                             float* __restrict__ out, int n_out) {
    __shared__ int      cnt[NL];
    __shared__ float    inv_s[NL];
    __shared__ float    xi[TI * NL], xj[TI * NL];
    __shared__ unsigned pmI[TI], pmJ[TI];
    __shared__ float    sxI[TI], sxJ[TI];
    __shared__ float    red[256];
    __shared__ int      is_last;

    const int tid = threadIdx.x;
    const int b   = blockIdx.x;
    const int bi  = b & (GB - 1);
    const int bj  = b >> 5;
    const int lid = tid & 31;

    if (tid < NL) cnt[tid] = 0;

    // Prediction tiles into shared
    xi[tid] = yp[bi * (TI * NL) + tid];
    xj[tid] = yp[bj * (TI * NL) + tid];
    __syncthreads();

    // --- per-block setup: masks for 2 rows per thread, label counts --------
    const int r0 = 2 * tid;              // rows r0, r0+1
    unsigned m0 = 0, m1 = 0;
    {
        const int4* y4 = (const int4*)(yt + r0 * NL);   // 8 consecutive int4
        #pragma unroll
        for (int q = 0; q < 4; q++) {
            int4 v = y4[q];
            if (v.x) m0 |= 1u << (4 * q + 0);
            if (v.y) m0 |= 1u << (4 * q + 1);
            if (v.z) m0 |= 1u << (4 * q + 2);
            if (v.w) m0 |= 1u << (4 * q + 3);
        }
        #pragma unroll
        for (int q = 0; q < 4; q++) {
            int4 v = y4[4 + q];
            if (v.x) m1 |= 1u << (4 * q + 0);
            if (v.y) m1 |= 1u << (4 * q + 1);
            if (v.z) m1 |= 1u << (4 * q + 2);
            if (v.w) m1 |= 1u << (4 * q + 3);
        }
    }

    // Publish masks for this block's i / j row tiles
    if (tid >= bi * 8 && tid < bi * 8 + 8) {
        int base = 2 * (tid - bi * 8);
        pmI[base] = m0; pmI[base + 1] = m1;
    }
    if (tid >= bj * 8 && tid < bj * 8 + 8) {
        int base = 2 * (tid - bj * 8);
        pmJ[base] = m0; pmJ[base + 1] = m1;
    }

    // n_pos per label: warp ballots + shared atomics
    #pragma unroll
    for (int l = 0; l < NL; l++) {
        unsigned b0 = __ballot_sync(0xffffffffu, (m0 >> l) & 1u);
        unsigned b1 = __ballot_sync(0xffffffffu, (m1 >> l) & 1u);
        if (lid == 0) atomicAdd(&cnt[l], __popc(b0) + __popc(b1));
    }
    __syncthreads();

    if (tid < NL) {
        int np = cnt[tid], nn = NROW - np;
        float d = (float)np * (float)nn;            // <= 2^18, exact
        inv_s[tid] = (np > 0 && nn > 0) ? 1.0f / (d * d * 256.0f) : 0.0f;
        float s = 0.0f;
        #pragma unroll
        for (int c = 0; c < NL; c++) s += xi[tid * NL + c];
        sxI[tid] = s;
    } else if (tid < 2 * NL) {
        int j = tid - NL;
        float s = 0.0f;
        #pragma unroll
        for (int c = 0; c < NL; c++) s += xj[j * NL + c];
        sxJ[j] = s;
    }
    __syncthreads();

    // --- main 16x16-pair loop: 1 packed f32x2 add per element pair ---------
    const int il = tid >> 4;
    const int jl = tid & 15;

    unsigned long long ci2[8];
    #pragma unroll
    for (int k = 0; k < 8; k++)
        ci2[k] = pk2(1.0f - xi[il * NL + 2 * k], 1.0f - xi[il * NL + 2 * k + 1]);

    const unsigned long long ABSM = 0x7FFFFFFF7FFFFFFFULL;
    unsigned long long sa0 = 0, sa1 = 0;

    #pragma unroll
    for (int d = 0; d < NL; d++) {
        float xq = xj[jl * NL + d];
        unsigned long long xq2 = pk2(xq, xq);
        #pragma unroll
        for (int k = 0; k < 8; k += 2) {
            unsigned long long t0 = addx2(ci2[k],     xq2) & ABSM;
            unsigned long long t1 = addx2(ci2[k + 1], xq2) & ABSM;
            sa0 = addx2(sa0, t0);
            sa1 = addx2(sa1, t1);
        }
    }

    float a0, a1, c0, c1;
    unpk2(sa0, a0, a1);
    unpk2(sa1, c0, c1);
    float s_abs = (a0 + a1) + (c0 + c1);
    float sum_t = 256.0f - 16.0f * sxI[il] + 16.0f * sxJ[jl];

    unsigned mask = pmI[il] & (~pmJ[jl]) & 0xFFFFu;
    float W = 0.0f;
    #pragma unroll
    for (int l = 0; l < NL; l++)
        if ((mask >> l) & 1u) W += inv_s[l];

    float contrib = W * 0.5f * (s_abs + sum_t);

    // --- block tree reduction (deterministic) -------------------------------
    red[tid] = contrib;
    __syncthreads();
    #pragma unroll
    for (int s = 128; s > 0; s >>= 1) {
        if (tid < s) red[tid] += red[tid + s];
        __syncthreads();
    }
    if (tid == 0) {
        g_part[b] = red[0];
        __threadfence();
        unsigned t = atomicAdd(&g_cnt, 1u);
        is_last = (t == NBLK - 1);
    }
    __syncthreads();

    // --- last block: final deterministic reduce + output --------------------
    if (is_last) {
        float v = g_part[tid] + g_part[tid + 256] + g_part[tid + 512] + g_part[tid + 768];
        red[tid] = v;
        __syncthreads();
        #pragma unroll
        for (int s = 128; s > 0; s >>= 1) {
            if (tid < s) red[tid] += red[tid + s];
            __syncthreads();
        }
        if (tid == 0) {
            out[0] = red[0];
            g_cnt = 0;                 // reset for next graph replay
        }
        for (int i = tid + 1; i < n_out; i += 256) out[i] = 0.0f;
    }
}

extern "C" void kernel_launch(void* const* d_in, const int* in_sizes, int n_in,
                              void* d_out, int out_size) {
    const int*   yt  = (const int*)d_in[0];    // y_true int32 [512*16]
    const float* yp  = (const float*)d_in[1];  // y_pred fp32  [512*16]
    float*       out = (float*)d_out;

    k_all<<<NBLK, 256>>>(yt, yp, out, out_size);
}

// round 4
// speedup vs baseline: 1.4156x; 1.4156x over previous
#include <cuda_runtime.h>

// B=512 rows, L=16 labels, N=8192 values.
// loss = sum_{i,j} W[i,j] * S[i,j]
//   W[i,j] = sum_l inv[l] * [yt[i,l]==1] * [yt[j,l]==0],  inv[l]=1/((np*nn)^2 * 256)
//   S[i,j] = 0.5 * ( sum|t| + 256 - 16*sx[i] + 16*sx[j] ),  t = 1 - x[i,c] + x[j,d]
// (relu(t) = (t+|t|)/2 exactly; sum t has a closed form.)
// Kernel A: one-time setup (masks, row sums, weight tables).
// Kernel B: 1024 blocks, 1 thread per row pair tile element; last block reduces.

#define NROW 512
#define NL   16
#define TI   16
#define GB   (NROW / TI)          // 32
#define NBLK (GB * GB)            // 1024

__device__ unsigned int g_pm[NROW];   // 16-bit positive mask per row
__device__ float        g_sx[NROW];   // per-row sum of yp
__device__ float        g_tlo[256];   // sum of inv[l], l<8, over set bits of index
__device__ float        g_thi[256];   // sum of inv[8+l] over set bits of index
__device__ float        g_part[NBLK];
__device__ unsigned int g_cnt = 0;

// ---- packed f32x2 helpers -------------------------------------------------
__device__ __forceinline__ unsigned long long pk2(float lo, float hi) {
    unsigned long long r;
    asm("mov.b64 %0, {%1, %2};" : "=l"(r) : "f"(lo), "f"(hi));
    return r;
}
__device__ __forceinline__ unsigned long long addx2(unsigned long long a,
                                                    unsigned long long b) {
    unsigned long long r;
    asm("add.rn.f32x2 %0, %1, %2;" : "=l"(r) : "l"(a), "l"(b));
    return r;
}
__device__ __forceinline__ void unpk2(unsigned long long v, float& lo, float& hi) {
    asm("mov.b64 {%0, %1}, %2;" : "=f"(lo), "=f"(hi) : "l"(v));
}

// ---------------------------------------------------------------------------
// Kernel A: one block, 512 threads, one row per thread. Masks + row sums via
// vector loads; n_pos via warp ballots + shared atomics; weight tables.
// ---------------------------------------------------------------------------
__global__ void __launch_bounds__(NROW) k_setup(const int* __restrict__ yt,
                                                const float* __restrict__ yp) {
    __shared__ int   cnt[NL];
    __shared__ float inv_s[NL];
    const int r   = threadIdx.x;   // row
    const int lid = r & 31;

    if (r < NL) cnt[r] = 0;
    __syncthreads();

    unsigned pm = 0;
    float sx = 0.0f;
    {
        const int4*   y4 = (const int4*)(yt + r * NL);
        const float4* p4 = (const float4*)(yp + r * NL);
        #pragma unroll
        for (int q = 0; q < 4; q++) {
            int4 yv = y4[q];
            if (yv.x) pm |= 1u << (4 * q + 0);
            if (yv.y) pm |= 1u << (4 * q + 1);
            if (yv.z) pm |= 1u << (4 * q + 2);
            if (yv.w) pm |= 1u << (4 * q + 3);
            float4 pv = p4[q];
            sx += (pv.x + pv.y) + (pv.z + pv.w);
        }
    }
    g_pm[r] = pm;
    g_sx[r] = sx;

    #pragma unroll
    for (int l = 0; l < NL; l++) {
        unsigned b = __ballot_sync(0xffffffffu, (pm >> l) & 1u);
        if (lid == 0) atomicAdd(&cnt[l], __popc(b));
    }
    __syncthreads();

    if (r < NL) {
        int np = cnt[r], nn = NROW - np;
        float d = (float)np * (float)nn;            // <= 2^18, exact in fp32
        inv_s[r] = (np > 0 && nn > 0) ? 1.0f / (d * d * 256.0f) : 0.0f;
    }
    __syncthreads();

    if (r < 256) {
        float lo = 0.0f, hi = 0.0f;
        #pragma unroll
        for (int l = 0; l < 8; l++) {
            if ((r >> l) & 1) { lo += inv_s[l]; hi += inv_s[8 + l]; }
        }
        g_tlo[r] = lo;
        g_thi[r] = hi;
    }
}

// ---------------------------------------------------------------------------
// Kernel B: grid 1024, block 256 — one thread per (i,j) row pair in a 16x16
// row tile; 128 packed f32x2 units (256 element pairs) per thread. Last block
// performs the final deterministic reduction and writes the output.
// ---------------------------------------------------------------------------
__global__ void __launch_bounds__(256) k_main(const float* __restrict__ yp,
                                              float* __restrict__ out, int n_out) {
    __shared__ float    xi[TI * NL], xj[TI * NL];
    __shared__ float    tlo_s[256], thi_s[256];
    __shared__ unsigned pmI[TI], nmJ[TI];
    __shared__ float    sxI[TI], sxJ[TI];
    __shared__ float    red[256];
    __shared__ int      is_last;

    const int b   = blockIdx.x;
    const int bi  = b & (GB - 1);
    const int bj  = b >> 5;
    const int tid = threadIdx.x;

    xi[tid]    = yp[bi * (TI * NL) + tid];
    xj[tid]    = yp[bj * (TI * NL) + tid];
    tlo_s[tid] = g_tlo[tid];
    thi_s[tid] = g_thi[tid];
    if (tid < TI) {
        pmI[tid] = g_pm[bi * TI + tid];
        sxI[tid] = g_sx[bi * TI + tid];
    } else if (tid < 2 * TI) {
        int j = tid - TI;
        nmJ[j] = (~g_pm[bj * TI + j]) & 0xFFFFu;
        sxJ[j] = g_sx[bj * TI + j];
    }
    __syncthreads();

    const int il = tid >> 4;
    const int jl = tid & 15;

    unsigned long long ci2[8];
    #pragma unroll
    for (int k = 0; k < 8; k++)
        ci2[k] = pk2(1.0f - xi[il * NL + 2 * k], 1.0f - xi[il * NL + 2 * k + 1]);

    const unsigned long long ABSM = 0x7FFFFFFF7FFFFFFFULL;
    unsigned long long sa0 = 0, sa1 = 0;

    #pragma unroll
    for (int d = 0; d < NL; d++) {
        float xq = xj[jl * NL + d];
        unsigned long long xq2 = pk2(xq, xq);
        #pragma unroll
        for (int k = 0; k < 8; k += 2) {
            unsigned long long t0 = addx2(ci2[k],     xq2) & ABSM;
            unsigned long long t1 = addx2(ci2[k + 1], xq2) & ABSM;
            sa0 = addx2(sa0, t0);
            sa1 = addx2(sa1, t1);
        }
    }

    float a0, a1, c0, c1;
    unpk2(sa0, a0, a1);
    unpk2(sa1, c0, c1);
    float s_abs = (a0 + a1) + (c0 + c1);
    float sum_t = 256.0f - 16.0f * sxI[il] + 16.0f * sxJ[jl];

    unsigned mask = pmI[il] & nmJ[jl];
    float W = tlo_s[mask & 255u] + thi_s[mask >> 8];
    float contrib = W * 0.5f * (s_abs + sum_t);

    // Block tree reduction (deterministic)
    red[tid] = contrib;
    __syncthreads();
    #pragma unroll
    for (int s = 128; s > 0; s >>= 1) {
        if (tid < s) red[tid] += red[tid + s];
        __syncthreads();
    }
    if (tid == 0) {
        g_part[b] = red[0];
        __threadfence();
        unsigned t = atomicAdd(&g_cnt, 1u);
        is_last = (t == NBLK - 1);
    }
    __syncthreads();

    // Last block: final deterministic reduce + output
    if (is_last) {
        float v = g_part[tid] + g_part[tid + 256] + g_part[tid + 512] + g_part[tid + 768];
        red[tid] = v;
        __syncthreads();
        #pragma unroll
        for (int s = 128; s > 0; s >>= 1) {
            if (tid < s) red[tid] += red[tid + s];
            __syncthreads();
        }
        if (tid == 0) {
            out[0] = red[0];
            g_cnt = 0;                 // reset for next graph replay
        }
        for (int i = tid + 1; i < n_out; i += 256) out[i] = 0.0f;
    }
}

extern "C" void kernel_launch(void* const* d_in, const int* in_sizes, int n_in,
                              void* d_out, int out_size) {
    const int*   yt  = (const int*)d_in[0];    // y_true int32 [512*16]
    const float* yp  = (const float*)d_in[1];  // y_pred fp32  [512*16]
    float*       out = (float*)d_out;

    k_setup<<<1, NROW>>>(yt, yp);
    k_main<<<NBLK, 256>>>(yp, out, out_size);
}